// round 1
// baseline (speedup 1.0000x reference)
#include <cuda_runtime.h>
#include <math.h>

#define NN 2000   // nodes
#define HH 512    // hidden
#define DD 256    // embed dim
#define RR 86     // relations

// Scratch (static device allocations are allowed)
__device__ float g_fpn[NN * HH];
__device__ float g_xfp[NN * DD];
__device__ float g_xskip[NN * DD];

__device__ __forceinline__ float elu1(float x) {
    return x > 0.f ? x : expm1f(x);
}

// ---------------------------------------------------------------------------
// Kernel 1: fp_n = elu(LayerNorm(drug_fp)), one warp per row (H=512)
// ---------------------------------------------------------------------------
__global__ void lnelu512_kernel(const float* __restrict__ in, float* __restrict__ out) {
    int gw   = (blockIdx.x * blockDim.x + threadIdx.x) >> 5;
    int lane = threadIdx.x & 31;
    if (gw >= NN) return;
    const float4* p = reinterpret_cast<const float4*>(in + (size_t)gw * HH);
    float4 v[4];
    float s = 0.f, q = 0.f;
#pragma unroll
    for (int i = 0; i < 4; ++i) {
        v[i] = p[lane + 32 * i];
        s += v[i].x + v[i].y + v[i].z + v[i].w;
        q = fmaf(v[i].x, v[i].x, q);
        q = fmaf(v[i].y, v[i].y, q);
        q = fmaf(v[i].z, v[i].z, q);
        q = fmaf(v[i].w, v[i].w, q);
    }
#pragma unroll
    for (int o = 16; o; o >>= 1) {
        s += __shfl_xor_sync(0xffffffffu, s, o);
        q += __shfl_xor_sync(0xffffffffu, q, o);
    }
    float m   = s * (1.f / HH);
    float var = fmaf(-m, m, q * (1.f / HH));
    float inv = rsqrtf(var + 1e-5f);
    float4* o4 = reinterpret_cast<float4*>(out + (size_t)gw * HH);
#pragma unroll
    for (int i = 0; i < 4; ++i) {
        float4 y;
        y.x = elu1((v[i].x - m) * inv);
        y.y = elu1((v[i].y - m) * inv);
        y.z = elu1((v[i].z - m) * inv);
        y.w = elu1((v[i].w - m) * inv);
        o4[lane + 32 * i] = y;
    }
}

// ---------------------------------------------------------------------------
// Kernel 2: C[n,d] = sum_h A[n,h] * W[d,h]   (optionally elu)
// A: [NN,HH] row-major, W: [DD,HH] row-major, C: [NN,DD]
// 64x64 tile, K-chunk 16, 256 threads, 4x4 register blocking
// ---------------------------------------------------------------------------
__global__ void __launch_bounds__(256)
gemm_nt_kernel(const float* __restrict__ A, const float* __restrict__ W,
               float* __restrict__ C, int doElu) {
    __shared__ float As[16][65];
    __shared__ float Ws[16][65];
    int tid = threadIdx.x;
    int tx = tid & 15, ty = tid >> 4;
    int n0 = blockIdx.x * 64, d0 = blockIdx.y * 64;
    float acc[4][4] = {};
    for (int h0 = 0; h0 < HH; h0 += 16) {
#pragma unroll
        for (int i = 0; i < 4; ++i) {
            int idx = tid + i * 256;
            int k = idx & 15, n = idx >> 4;
            int gn = n0 + n;
            As[k][n] = (gn < NN) ? A[(size_t)gn * HH + h0 + k] : 0.f;
            Ws[k][n] = W[(size_t)(d0 + n) * HH + h0 + k];
        }
        __syncthreads();
#pragma unroll
        for (int k = 0; k < 16; ++k) {
            float a[4], b[4];
#pragma unroll
            for (int i = 0; i < 4; ++i) a[i] = As[k][ty + 16 * i];
#pragma unroll
            for (int j = 0; j < 4; ++j) b[j] = Ws[k][tx + 16 * j];
#pragma unroll
            for (int i = 0; i < 4; ++i)
#pragma unroll
                for (int j = 0; j < 4; ++j)
                    acc[i][j] = fmaf(a[i], b[j], acc[i][j]);
        }
        __syncthreads();
    }
#pragma unroll
    for (int i = 0; i < 4; ++i) {
        int n = n0 + ty + 16 * i;
        if (n >= NN) continue;
#pragma unroll
        for (int j = 0; j < 4; ++j) {
            float v = acc[i][j];
            if (doElu) v = elu1(v);
            C[(size_t)n * DD + d0 + tx + 16 * j] = v;
        }
    }
}

// ---------------------------------------------------------------------------
// Kernel 3: edge phase. One warp per edge; lane owns 8 floats (2x float4).
// Relation weights pre-combined (wA = wr-wi, wB = wr+wi) staged in SMEM.
// ---------------------------------------------------------------------------
struct V8 { float v[8]; };

__device__ __forceinline__ V8 ldrow(const float* __restrict__ base, int row, int lane) {
    const float4* p = reinterpret_cast<const float4*>(base + ((size_t)row << 8));
    float4 a = p[lane];
    float4 b = p[lane + 32];
    V8 r;
    r.v[0] = a.x; r.v[1] = a.y; r.v[2] = a.z; r.v[3] = a.w;
    r.v[4] = b.x; r.v[5] = b.y; r.v[6] = b.z; r.v[7] = b.w;
    return r;
}

__device__ __forceinline__ void lnorm(V8& x) {
    float s = 0.f, q = 0.f;
#pragma unroll
    for (int i = 0; i < 8; ++i) {
        s += x.v[i];
        q = fmaf(x.v[i], x.v[i], q);
    }
#pragma unroll
    for (int o = 16; o; o >>= 1) {
        s += __shfl_xor_sync(0xffffffffu, s, o);
        q += __shfl_xor_sync(0xffffffffu, q, o);
    }
    float m   = s * (1.f / DD);
    float var = fmaf(-m, m, q * (1.f / DD));
    float inv = rsqrtf(var + 1e-5f);
#pragma unroll
    for (int i = 0; i < 8; ++i) x.v[i] = (x.v[i] - m) * inv;
}

__global__ void __launch_bounds__(512, 1)
edge_kernel(const float* __restrict__ x1, const float* __restrict__ x2,
            const float* __restrict__ xfp, const float* __restrict__ xskip,
            const float* __restrict__ wr, const float* __restrict__ wi,
            const int* __restrict__ idx1, const int* __restrict__ idx2,
            const int* __restrict__ idx3,
            float* __restrict__ out, int E) {
    extern __shared__ float sw[];  // [0, RR*DD): wA = wr-wi ; [RR*DD, 2*RR*DD): wB = wr+wi
    for (int i = threadIdx.x; i < RR * DD; i += blockDim.x) {
        float a = wr[i], b = wi[i];
        sw[i]           = a - b;
        sw[RR * DD + i] = a + b;
    }
    __syncthreads();

    int lane = threadIdx.x & 31;
    int warp = threadIdx.x >> 5;
    int gw = blockIdx.x * (blockDim.x >> 5) + warp;
    int nw = gridDim.x * (blockDim.x >> 5);

    for (int e = gw; e < E; e += nw) {
        int i1 = idx1[e], i2 = idx2[e], rr = idx3[e];

        // Issue all 16 LDG.128 up front (MLP)
        V8 a_x1i1 = ldrow(x1,    i1, lane);
        V8 a_x2i1 = ldrow(x2,    i1, lane);
        V8 a_fpi1 = ldrow(xfp,   i1, lane);
        V8 a_ski1 = ldrow(xskip, i1, lane);
        V8 a_x1i2 = ldrow(x1,    i2, lane);
        V8 a_x2i2 = ldrow(x2,    i2, lane);
        V8 a_fpi2 = ldrow(xfp,   i2, lane);
        V8 a_ski2 = ldrow(xskip, i2, lane);

        V8 R1, I1, R2, I2;
#pragma unroll
        for (int i = 0; i < 8; ++i) {
            R1.v[i] = a_x1i1.v[i] + a_fpi2.v[i];
            I1.v[i] = a_x2i1.v[i] + a_ski2.v[i];
            R2.v[i] = a_ski1.v[i] + a_x2i2.v[i];
            I2.v[i] = a_fpi1.v[i] + a_x1i2.v[i];
        }
        lnorm(R1); lnorm(I1); lnorm(R2); lnorm(I2);

        V8 Rc, Ic;
#pragma unroll
        for (int i = 0; i < 8; ++i) {
            Rc.v[i] = fmaf(R1.v[i], R2.v[i], -I1.v[i] * I2.v[i]);
            Ic.v[i] = fmaf(R1.v[i], I2.v[i],  I1.v[i] * R2.v[i]);
        }
        lnorm(Rc); lnorm(Ic);

        // r_ + i_ = sum(Rc*(wr-wi)) + sum(Ic*(wr+wi))
        const float4* wAp = reinterpret_cast<const float4*>(sw) + rr * 64;
        const float4* wBp = reinterpret_cast<const float4*>(sw + RR * DD) + rr * 64;
        float4 wa0 = wAp[lane], wa1 = wAp[lane + 32];
        float4 wb0 = wBp[lane], wb1 = wBp[lane + 32];
        float wa[8] = {wa0.x, wa0.y, wa0.z, wa0.w, wa1.x, wa1.y, wa1.z, wa1.w};
        float wb[8] = {wb0.x, wb0.y, wb0.z, wb0.w, wb1.x, wb1.y, wb1.z, wb1.w};

        float acc = 0.f;
#pragma unroll
        for (int i = 0; i < 8; ++i) {
            acc = fmaf(Rc.v[i], wa[i], acc);
            acc = fmaf(Ic.v[i], wb[i], acc);
        }
#pragma unroll
        for (int o = 16; o; o >>= 1) acc += __shfl_xor_sync(0xffffffffu, acc, o);

        if (lane == 0) out[e] = 1.f / (1.f + expf(-acc));
    }
}

// ---------------------------------------------------------------------------
extern "C" void kernel_launch(void* const* d_in, const int* in_sizes, int n_in,
                              void* d_out, int out_size) {
    const float* drug_fp   = (const float*)d_in[0];
    const float* drug_init = (const float*)d_in[1];
    const float* x1        = (const float*)d_in[2];
    const float* x2        = (const float*)d_in[3];
    const float* W_fp      = (const float*)d_in[4];
    const float* W_skip    = (const float*)d_in[5];
    const float* wr        = (const float*)d_in[6];
    const float* wi        = (const float*)d_in[7];
    const int*   idx1      = (const int*)d_in[8];
    const int*   idx2      = (const int*)d_in[9];
    const int*   idx3      = (const int*)d_in[10];
    float*       out       = (float*)d_out;
    int E = in_sizes[8];

    float *fpn, *xfp, *xskip;
    cudaGetSymbolAddress((void**)&fpn,   g_fpn);
    cudaGetSymbolAddress((void**)&xfp,   g_xfp);
    cudaGetSymbolAddress((void**)&xskip, g_xskip);

    // 1) fp_n = elu(LN(drug_fp))
    lnelu512_kernel<<<(NN * 32 + 255) / 256, 256>>>(drug_fp, fpn);

    // 2) x_fp = elu(fp_n @ W_fp^T) ; x_skip = drug_init @ W_skip^T
    dim3 gg((NN + 63) / 64, DD / 64);
    gemm_nt_kernel<<<gg, 256>>>(fpn,       W_fp,   xfp,   1);
    gemm_nt_kernel<<<gg, 256>>>(drug_init, W_skip, xskip, 0);

    // 3) edge phase
    int smem = 2 * RR * DD * (int)sizeof(float);  // 176128 B
    cudaFuncSetAttribute(edge_kernel, cudaFuncAttributeMaxDynamicSharedMemorySize, smem);
    edge_kernel<<<148, 512, smem>>>(x1, x2, xfp, xskip, wr, wi,
                                    idx1, idx2, idx3, out, E);
}

// round 2
// speedup vs baseline: 1.2461x; 1.2461x over previous
#include <cuda_runtime.h>
#include <math.h>

#define NN 2000   // nodes
#define HH 512    // hidden
#define DD 256    // embed dim
#define RR 86     // relations

// Scratch
__device__ float g_fpn[NN * HH];
__device__ float g_P[NN * 4 * DD];    // per node: [x1 | x2 | xfp | xskip]
__device__ float g_wAB[RR * 2 * DD];  // per relation: [wr-wi | wr+wi]

__device__ __forceinline__ float elu1(float x) {
    return x > 0.f ? x : expm1f(x);
}

// ---------------------------------------------------------------------------
// Kernel 1: fp_n = elu(LayerNorm(drug_fp)), one warp per row (H=512)
// ---------------------------------------------------------------------------
__global__ void lnelu512_kernel(const float* __restrict__ in, float* __restrict__ out) {
    int gw   = (blockIdx.x * blockDim.x + threadIdx.x) >> 5;
    int lane = threadIdx.x & 31;
    if (gw >= NN) return;
    const float4* p = reinterpret_cast<const float4*>(in + (size_t)gw * HH);
    float4 v[4];
    float s = 0.f, q = 0.f;
#pragma unroll
    for (int i = 0; i < 4; ++i) {
        v[i] = p[lane + 32 * i];
        s += v[i].x + v[i].y + v[i].z + v[i].w;
        q = fmaf(v[i].x, v[i].x, q);
        q = fmaf(v[i].y, v[i].y, q);
        q = fmaf(v[i].z, v[i].z, q);
        q = fmaf(v[i].w, v[i].w, q);
    }
#pragma unroll
    for (int o = 16; o; o >>= 1) {
        s += __shfl_xor_sync(0xffffffffu, s, o);
        q += __shfl_xor_sync(0xffffffffu, q, o);
    }
    float m   = s * (1.f / HH);
    float var = fmaf(-m, m, q * (1.f / HH));
    float inv = rsqrtf(var + 1e-5f);
    float4* o4 = reinterpret_cast<float4*>(out + (size_t)gw * HH);
#pragma unroll
    for (int i = 0; i < 4; ++i) {
        float4 y;
        y.x = elu1((v[i].x - m) * inv);
        y.y = elu1((v[i].y - m) * inv);
        y.z = elu1((v[i].z - m) * inv);
        y.w = elu1((v[i].w - m) * inv);
        o4[lane + 32 * i] = y;
    }
}

// ---------------------------------------------------------------------------
// Kernel 2: pack x1/x2 into P, precombine relation weights
// ---------------------------------------------------------------------------
__global__ void pack_kernel(const float* __restrict__ x1, const float* __restrict__ x2,
                            const float* __restrict__ wr, const float* __restrict__ wi,
                            float* __restrict__ P, float* __restrict__ wAB) {
    int i = blockIdx.x * blockDim.x + threadIdx.x;
    if (i < NN * DD) {
        int n = i >> 8, d = i & 255;
        P[(size_t)n * (4 * DD) + d]       = x1[i];
        P[(size_t)n * (4 * DD) + DD + d]  = x2[i];
    }
    if (i < RR * DD) {
        int r = i >> 8, d = i & 255;
        float a = wr[i], b = wi[i];
        wAB[(size_t)r * (2 * DD) + d]      = a - b;
        wAB[(size_t)r * (2 * DD) + DD + d] = a + b;
    }
}

// ---------------------------------------------------------------------------
// Kernel 3: C[n,slot,d] = (elu?)(sum_h A[n,h] * W[d,h]) written into P layout.
// z=0: A0/W0 -> slot 2 with elu ; z=1: A1/W1 -> slot 3
// ---------------------------------------------------------------------------
__global__ void __launch_bounds__(256)
gemm_nt_kernel(const float* __restrict__ A0, const float* __restrict__ W0,
               const float* __restrict__ A1, const float* __restrict__ W1,
               float* __restrict__ P) {
    __shared__ float As[16][65];
    __shared__ float Ws[16][65];
    const float* A = blockIdx.z ? A1 : A0;
    const float* W = blockIdx.z ? W1 : W0;
    int slot = blockIdx.z ? 3 : 2;
    int doElu = blockIdx.z ? 0 : 1;
    int tid = threadIdx.x;
    int tx = tid & 15, ty = tid >> 4;
    int n0 = blockIdx.x * 64, d0 = blockIdx.y * 64;
    float acc[4][4] = {};
    for (int h0 = 0; h0 < HH; h0 += 16) {
#pragma unroll
        for (int i = 0; i < 4; ++i) {
            int idx = tid + i * 256;
            int k = idx & 15, n = idx >> 4;
            int gn = n0 + n;
            As[k][n] = (gn < NN) ? A[(size_t)gn * HH + h0 + k] : 0.f;
            Ws[k][n] = W[(size_t)(d0 + n) * HH + h0 + k];
        }
        __syncthreads();
#pragma unroll
        for (int k = 0; k < 16; ++k) {
            float a[4], b[4];
#pragma unroll
            for (int i = 0; i < 4; ++i) a[i] = As[k][ty + 16 * i];
#pragma unroll
            for (int j = 0; j < 4; ++j) b[j] = Ws[k][tx + 16 * j];
#pragma unroll
            for (int i = 0; i < 4; ++i)
#pragma unroll
                for (int j = 0; j < 4; ++j)
                    acc[i][j] = fmaf(a[i], b[j], acc[i][j]);
        }
        __syncthreads();
    }
#pragma unroll
    for (int i = 0; i < 4; ++i) {
        int n = n0 + ty + 16 * i;
        if (n >= NN) continue;
#pragma unroll
        for (int j = 0; j < 4; ++j) {
            float v = acc[i][j];
            if (doElu) v = elu1(v);
            P[(size_t)n * (4 * DD) + slot * DD + d0 + tx + 16 * j] = v;
        }
    }
}

// ---------------------------------------------------------------------------
// Kernel 4: edge phase. One warp per edge; lane owns 8 floats (2x float4).
// Fused butterflies: one 8-acc tree for R1/I1/R2/I2, one 4-acc tree for Rc/Ic.
// ---------------------------------------------------------------------------
#define ADD4(r, a, b) { r.x = a.x + b.x; r.y = a.y + b.y; r.z = a.z + b.z; r.w = a.w + b.w; }

__device__ __forceinline__ void stat4(const float4& v, float& s, float& q) {
    s += v.x + v.y + v.z + v.w;
    q = fmaf(v.x, v.x, q);
    q = fmaf(v.y, v.y, q);
    q = fmaf(v.z, v.z, q);
    q = fmaf(v.w, v.w, q);
}
__device__ __forceinline__ void scale4(float4& v, float m, float inv) {
    v.x = (v.x - m) * inv;
    v.y = (v.y - m) * inv;
    v.z = (v.z - m) * inv;
    v.w = (v.w - m) * inv;
}

__global__ void __launch_bounds__(256, 3)
edge_kernel(const float* __restrict__ Pf, const float* __restrict__ wABf,
            const int* __restrict__ idx1, const int* __restrict__ idx2,
            const int* __restrict__ idx3,
            float* __restrict__ out, int E) {
    int gw = (blockIdx.x * blockDim.x + threadIdx.x) >> 5;
    if (gw >= E) return;
    int lane = threadIdx.x & 31;

    const float4* p1 = reinterpret_cast<const float4*>(Pf) + ((size_t)idx1[gw] << 8);
    const float4* p2 = reinterpret_cast<const float4*>(Pf) + ((size_t)idx2[gw] << 8);
    int rr = idx3[gw];

    // slots (float4 units): x1=0, x2=64, xfp=128, xskip=192; halves: +lane, +lane+32
    float4 R1[2], I1[2], R2[2], I2[2];
#pragma unroll
    for (int h = 0; h < 2; ++h) {
        int o = lane + h * 32;
        float4 t0 = p1[o];          // x1[i1]
        float4 t1 = p2[128 + o];    // xfp[i2]
        float4 t2 = p1[64 + o];     // x2[i1]
        float4 t3 = p2[192 + o];    // xskip[i2]
        float4 t4 = p1[192 + o];    // xskip[i1]
        float4 t5 = p2[64 + o];     // x2[i2]
        float4 t6 = p1[128 + o];    // xfp[i1]
        float4 t7 = p2[o];          // x1[i2]
        ADD4(R1[h], t0, t1);
        ADD4(I1[h], t2, t3);
        ADD4(R2[h], t4, t5);
        ADD4(I2[h], t6, t7);
    }

    // Fused stats for 4 LNs: 8 accumulators, one butterfly
    float s[4] = {}, q[4] = {};
#pragma unroll
    for (int h = 0; h < 2; ++h) {
        stat4(R1[h], s[0], q[0]);
        stat4(I1[h], s[1], q[1]);
        stat4(R2[h], s[2], q[2]);
        stat4(I2[h], s[3], q[3]);
    }
#pragma unroll
    for (int o = 16; o; o >>= 1) {
#pragma unroll
        for (int k = 0; k < 4; ++k) {
            s[k] += __shfl_xor_sync(0xffffffffu, s[k], o);
            q[k] += __shfl_xor_sync(0xffffffffu, q[k], o);
        }
    }
    float m[4], inv[4];
#pragma unroll
    for (int k = 0; k < 4; ++k) {
        m[k] = s[k] * (1.f / DD);
        float var = fmaf(-m[k], m[k], q[k] * (1.f / DD));
        inv[k] = rsqrtf(var + 1e-5f);
    }
#pragma unroll
    for (int h = 0; h < 2; ++h) {
        scale4(R1[h], m[0], inv[0]);
        scale4(I1[h], m[1], inv[1]);
        scale4(R2[h], m[2], inv[2]);
        scale4(I2[h], m[3], inv[3]);
    }

    // Complex multiply
    float4 Rc[2], Ic[2];
#pragma unroll
    for (int h = 0; h < 2; ++h) {
        Rc[h].x = fmaf(R1[h].x, R2[h].x, -I1[h].x * I2[h].x);
        Rc[h].y = fmaf(R1[h].y, R2[h].y, -I1[h].y * I2[h].y);
        Rc[h].z = fmaf(R1[h].z, R2[h].z, -I1[h].z * I2[h].z);
        Rc[h].w = fmaf(R1[h].w, R2[h].w, -I1[h].w * I2[h].w);
        Ic[h].x = fmaf(R1[h].x, I2[h].x, I1[h].x * R2[h].x);
        Ic[h].y = fmaf(R1[h].y, I2[h].y, I1[h].y * R2[h].y);
        Ic[h].z = fmaf(R1[h].z, I2[h].z, I1[h].z * R2[h].z);
        Ic[h].w = fmaf(R1[h].w, I2[h].w, I1[h].w * R2[h].w);
    }

    // Fused stats for Rc/Ic: 4 accumulators, one butterfly
    float s2[2] = {}, q2[2] = {};
#pragma unroll
    for (int h = 0; h < 2; ++h) {
        stat4(Rc[h], s2[0], q2[0]);
        stat4(Ic[h], s2[1], q2[1]);
    }
#pragma unroll
    for (int o = 16; o; o >>= 1) {
#pragma unroll
        for (int k = 0; k < 2; ++k) {
            s2[k] += __shfl_xor_sync(0xffffffffu, s2[k], o);
            q2[k] += __shfl_xor_sync(0xffffffffu, q2[k], o);
        }
    }
    float m2[2], inv2[2];
#pragma unroll
    for (int k = 0; k < 2; ++k) {
        m2[k] = s2[k] * (1.f / DD);
        float var = fmaf(-m2[k], m2[k], q2[k] * (1.f / DD));
        inv2[k] = rsqrtf(var + 1e-5f);
    }

    // Dot with precombined relation weights; LN of Rc/Ic folded in algebraically:
    // sum((Rc-m)*inv * wA) = inv*(sum(Rc*wA) - m*sum(wA))
    const float4* wp = reinterpret_cast<const float4*>(wABf) + ((size_t)rr << 7);
    float dA = 0.f, dB = 0.f, sA = 0.f, sB = 0.f;
#pragma unroll
    for (int h = 0; h < 2; ++h) {
        int o = lane + h * 32;
        float4 wa = wp[o];
        float4 wb = wp[64 + o];
        dA = fmaf(Rc[h].x, wa.x, dA); dA = fmaf(Rc[h].y, wa.y, dA);
        dA = fmaf(Rc[h].z, wa.z, dA); dA = fmaf(Rc[h].w, wa.w, dA);
        dB = fmaf(Ic[h].x, wb.x, dB); dB = fmaf(Ic[h].y, wb.y, dB);
        dB = fmaf(Ic[h].z, wb.z, dB); dB = fmaf(Ic[h].w, wb.w, dB);
        sA += wa.x + wa.y + wa.z + wa.w;
        sB += wb.x + wb.y + wb.z + wb.w;
    }
    float acc = fmaf(dA, inv2[0], -m2[0] * inv2[0] * sA)
              + fmaf(dB, inv2[1], -m2[1] * inv2[1] * sB);
#pragma unroll
    for (int o = 16; o; o >>= 1) acc += __shfl_xor_sync(0xffffffffu, acc, o);

    if (lane == 0) out[gw] = 1.f / (1.f + expf(-acc));
}

// ---------------------------------------------------------------------------
extern "C" void kernel_launch(void* const* d_in, const int* in_sizes, int n_in,
                              void* d_out, int out_size) {
    const float* drug_fp   = (const float*)d_in[0];
    const float* drug_init = (const float*)d_in[1];
    const float* x1        = (const float*)d_in[2];
    const float* x2        = (const float*)d_in[3];
    const float* W_fp      = (const float*)d_in[4];
    const float* W_skip    = (const float*)d_in[5];
    const float* wr        = (const float*)d_in[6];
    const float* wi        = (const float*)d_in[7];
    const int*   idx1      = (const int*)d_in[8];
    const int*   idx2      = (const int*)d_in[9];
    const int*   idx3      = (const int*)d_in[10];
    float*       out       = (float*)d_out;
    int E = in_sizes[8];

    float *fpn, *P, *wAB;
    cudaGetSymbolAddress((void**)&fpn, g_fpn);
    cudaGetSymbolAddress((void**)&P,   g_P);
    cudaGetSymbolAddress((void**)&wAB, g_wAB);

    // 1) fp_n = elu(LN(drug_fp))
    lnelu512_kernel<<<(NN * 32 + 255) / 256, 256>>>(drug_fp, fpn);

    // 2) pack x1/x2 and relation weights
    pack_kernel<<<(NN * DD + 255) / 256, 256>>>(x1, x2, wr, wi, P, wAB);

    // 3) GEMMs -> slots 2/3 of P
    dim3 gg((NN + 63) / 64, DD / 64, 2);
    gemm_nt_kernel<<<gg, 256>>>(fpn, W_fp, drug_init, W_skip, P);

    // 4) edge phase: one warp per edge
    int nwarp_blocks = (E + 7) / 8;  // 8 warps per 256-thread block
    edge_kernel<<<nwarp_blocks, 256>>>(P, wAB, idx1, idx2, idx3, out, E);
}

// round 4
// speedup vs baseline: 1.2989x; 1.0424x over previous
#include <cuda_runtime.h>
#include <math.h>

#define NN 2000   // nodes
#define HH 512    // hidden
#define DD 256    // embed dim
#define RR 86     // relations

// Scratch
__device__ float g_fpn[NN * HH];
__device__ float g_P[NN * 4 * DD];     // per node: [x1 | x2 | xfp | xskip]
__device__ float g_wAB[RR * 2 * DD];   // per relation: [wr-wi | wr+wi]
__device__ float g_NS[NN * 8];         // per node: S[4], Q[4]
__device__ float g_RS[RR * 2];         // per relation: sum(wA), sum(wB)

__device__ __forceinline__ float elu1(float x) {
    return x > 0.f ? x : expm1f(x);
}
__device__ __forceinline__ float sum4(const float4& v) {
    return (v.x + v.y) + (v.z + v.w);
}
__device__ __forceinline__ float sq4(const float4& v) {
    float q = v.x * v.x;
    q = fmaf(v.y, v.y, q);
    q = fmaf(v.z, v.z, q);
    q = fmaf(v.w, v.w, q);
    return q;
}
__device__ __forceinline__ float dot4(const float4& a, const float4& b) {
    float d = a.x * b.x;
    d = fmaf(a.y, b.y, d);
    d = fmaf(a.z, b.z, d);
    d = fmaf(a.w, b.w, d);
    return d;
}

// ---------------------------------------------------------------------------
// Kernel 1: fp_n = elu(LayerNorm(drug_fp)), one warp per row (H=512)
// ---------------------------------------------------------------------------
__global__ void lnelu512_kernel(const float* __restrict__ in, float* __restrict__ out) {
    int gw   = (blockIdx.x * blockDim.x + threadIdx.x) >> 5;
    int lane = threadIdx.x & 31;
    if (gw >= NN) return;
    const float4* p = reinterpret_cast<const float4*>(in + (size_t)gw * HH);
    float4 v[4];
    float s = 0.f, q = 0.f;
#pragma unroll
    for (int i = 0; i < 4; ++i) {
        v[i] = p[lane + 32 * i];
        s += sum4(v[i]);
        q += sq4(v[i]);
    }
#pragma unroll
    for (int o = 16; o; o >>= 1) {
        s += __shfl_xor_sync(0xffffffffu, s, o);
        q += __shfl_xor_sync(0xffffffffu, q, o);
    }
    float m   = s * (1.f / HH);
    float var = fmaf(-m, m, q * (1.f / HH));
    float inv = rsqrtf(var + 1e-5f);
    float4* o4 = reinterpret_cast<float4*>(out + (size_t)gw * HH);
#pragma unroll
    for (int i = 0; i < 4; ++i) {
        float4 y;
        y.x = elu1((v[i].x - m) * inv);
        y.y = elu1((v[i].y - m) * inv);
        y.z = elu1((v[i].z - m) * inv);
        y.w = elu1((v[i].w - m) * inv);
        o4[lane + 32 * i] = y;
    }
}

// ---------------------------------------------------------------------------
// Kernel 2: pack x1/x2 into P, precombine relation weights
// ---------------------------------------------------------------------------
__global__ void pack_kernel(const float* __restrict__ x1, const float* __restrict__ x2,
                            const float* __restrict__ wr, const float* __restrict__ wi,
                            float* __restrict__ P, float* __restrict__ wAB) {
    int i = blockIdx.x * blockDim.x + threadIdx.x;
    if (i < NN * DD) {
        int n = i >> 8, d = i & 255;
        P[(size_t)n * (4 * DD) + d]       = x1[i];
        P[(size_t)n * (4 * DD) + DD + d]  = x2[i];
    }
    if (i < RR * DD) {
        int r = i >> 8, d = i & 255;
        float a = wr[i], b = wi[i];
        wAB[(size_t)r * (2 * DD) + d]      = a - b;
        wAB[(size_t)r * (2 * DD) + DD + d] = a + b;
    }
}

// ---------------------------------------------------------------------------
// Kernel 3: GEMM C[n,slot,d] = (elu?)(sum_h A[n,h] * W[d,h]) into P layout.
// ---------------------------------------------------------------------------
__global__ void __launch_bounds__(256)
gemm_nt_kernel(const float* __restrict__ A0, const float* __restrict__ W0,
               const float* __restrict__ A1, const float* __restrict__ W1,
               float* __restrict__ P) {
    __shared__ float As[16][65];
    __shared__ float Ws[16][65];
    const float* A = blockIdx.z ? A1 : A0;
    const float* W = blockIdx.z ? W1 : W0;
    int slot = blockIdx.z ? 3 : 2;
    int doElu = blockIdx.z ? 0 : 1;
    int tid = threadIdx.x;
    int tx = tid & 15, ty = tid >> 4;
    int n0 = blockIdx.x * 64, d0 = blockIdx.y * 64;
    float acc[4][4] = {};
    for (int h0 = 0; h0 < HH; h0 += 16) {
#pragma unroll
        for (int i = 0; i < 4; ++i) {
            int idx = tid + i * 256;
            int k = idx & 15, n = idx >> 4;
            int gn = n0 + n;
            As[k][n] = (gn < NN) ? A[(size_t)gn * HH + h0 + k] : 0.f;
            Ws[k][n] = W[(size_t)(d0 + n) * HH + h0 + k];
        }
        __syncthreads();
#pragma unroll
        for (int k = 0; k < 16; ++k) {
            float a[4], b[4];
#pragma unroll
            for (int i = 0; i < 4; ++i) a[i] = As[k][ty + 16 * i];
#pragma unroll
            for (int j = 0; j < 4; ++j) b[j] = Ws[k][tx + 16 * j];
#pragma unroll
            for (int i = 0; i < 4; ++i)
#pragma unroll
                for (int j = 0; j < 4; ++j)
                    acc[i][j] = fmaf(a[i], b[j], acc[i][j]);
        }
        __syncthreads();
    }
#pragma unroll
    for (int i = 0; i < 4; ++i) {
        int n = n0 + ty + 16 * i;
        if (n >= NN) continue;
#pragma unroll
        for (int j = 0; j < 4; ++j) {
            float v = acc[i][j];
            if (doElu) v = elu1(v);
            P[(size_t)n * (4 * DD) + slot * DD + d0 + tx + 16 * j] = v;
        }
    }
}

// ---------------------------------------------------------------------------
// Kernel 4: per-node stats (sum, sumsq per slot). One warp per node.
// ---------------------------------------------------------------------------
__global__ void nodestat_kernel(const float* __restrict__ P, float* __restrict__ NS) {
    int gw   = (blockIdx.x * blockDim.x + threadIdx.x) >> 5;
    int lane = threadIdx.x & 31;
    if (gw >= NN) return;
    const float4* p = reinterpret_cast<const float4*>(P) + ((size_t)gw << 8);
    float s[4], q[4];
#pragma unroll
    for (int k = 0; k < 4; ++k) {
        float4 a = p[k * 64 + lane];
        float4 b = p[k * 64 + lane + 32];
        s[k] = sum4(a) + sum4(b);
        q[k] = sq4(a) + sq4(b);
    }
#pragma unroll
    for (int o = 16; o; o >>= 1) {
#pragma unroll
        for (int k = 0; k < 4; ++k) {
            s[k] += __shfl_xor_sync(0xffffffffu, s[k], o);
            q[k] += __shfl_xor_sync(0xffffffffu, q[k], o);
        }
    }
    if (lane == 0) {
#pragma unroll
        for (int k = 0; k < 4; ++k) {
            NS[gw * 8 + k]     = s[k];
            NS[gw * 8 + 4 + k] = q[k];
        }
    }
}

// ---------------------------------------------------------------------------
// Kernel 5: per-relation weight sums. One warp per relation.
// ---------------------------------------------------------------------------
__global__ void relstat_kernel(const float* __restrict__ wAB, float* __restrict__ RS) {
    int gw   = (blockIdx.x * blockDim.x + threadIdx.x) >> 5;
    int lane = threadIdx.x & 31;
    if (gw >= RR) return;
    const float4* p = reinterpret_cast<const float4*>(wAB) + ((size_t)gw << 7);
    float sA = sum4(p[lane]) + sum4(p[lane + 32]);
    float sB = sum4(p[64 + lane]) + sum4(p[64 + lane + 32]);
#pragma unroll
    for (int o = 16; o; o >>= 1) {
        sA += __shfl_xor_sync(0xffffffffu, sA, o);
        sB += __shfl_xor_sync(0xffffffffu, sB, o);
    }
    if (lane == 0) {
        RS[gw * 2]     = sA;
        RS[gw * 2 + 1] = sB;
    }
}

// ---------------------------------------------------------------------------
// Kernel 6: edge phase. One warp per edge, lane owns 8 floats.
// Tree A: 4 cross-dots only (means/sumsqs precomputed per node).
// Tree B: {s2,q2 of Rc,Ic} + {dA,dB} fused (weight sums precomputed).
// ---------------------------------------------------------------------------
__global__ void __launch_bounds__(256, 4)
edge_kernel(const float* __restrict__ Pf, const float* __restrict__ wABf,
            const float* __restrict__ NS, const float* __restrict__ RS,
            const int* __restrict__ idx1, const int* __restrict__ idx2,
            const int* __restrict__ idx3,
            float* __restrict__ out, int E) {
    int gw = (blockIdx.x * blockDim.x + threadIdx.x) >> 5;
    if (gw >= E) return;
    int lane = threadIdx.x & 31;

    int i1 = idx1[gw], i2 = idx2[gw], rr = idx3[gw];
    const float4* p1 = reinterpret_cast<const float4*>(Pf) + ((size_t)i1 << 8);
    const float4* p2 = reinterpret_cast<const float4*>(Pf) + ((size_t)i2 << 8);

    // node stats (uniform across warp; broadcast loads)
    const float4* ns1 = reinterpret_cast<const float4*>(NS + i1 * 8);
    const float4* ns2 = reinterpret_cast<const float4*>(NS + i2 * 8);
    float4 S1 = ns1[0], Q1 = ns1[1];
    float4 S2 = ns2[0], Q2 = ns2[1];

    // slots (float4 units): x1=0, x2=64, xfp=128, xskip=192
    float4 R1[2], I1[2], R2[2], I2[2];
    float d0 = 0.f, d1 = 0.f, d2 = 0.f, d3 = 0.f;
#pragma unroll
    for (int h = 0; h < 2; ++h) {
        int o = lane + h * 32;
        float4 a0 = p1[o];          // x1[i1]
        float4 b0 = p2[128 + o];    // xfp[i2]
        float4 a1 = p1[64 + o];     // x2[i1]
        float4 b1 = p2[192 + o];    // xskip[i2]
        float4 a2 = p1[192 + o];    // xskip[i1]
        float4 b2 = p2[64 + o];     // x2[i2]
        float4 a3 = p1[128 + o];    // xfp[i1]
        float4 b3 = p2[o];          // x1[i2]
        R1[h].x = a0.x + b0.x; R1[h].y = a0.y + b0.y; R1[h].z = a0.z + b0.z; R1[h].w = a0.w + b0.w;
        I1[h].x = a1.x + b1.x; I1[h].y = a1.y + b1.y; I1[h].z = a1.z + b1.z; I1[h].w = a1.w + b1.w;
        R2[h].x = a2.x + b2.x; R2[h].y = a2.y + b2.y; R2[h].z = a2.z + b2.z; R2[h].w = a2.w + b2.w;
        I2[h].x = a3.x + b3.x; I2[h].y = a3.y + b3.y; I2[h].z = a3.z + b3.z; I2[h].w = a3.w + b3.w;
        d0 += dot4(a0, b0);
        d1 += dot4(a1, b1);
        d2 += dot4(a2, b2);
        d3 += dot4(a3, b3);
    }

    // Tree A: reduce the 4 cross dots
#pragma unroll
    for (int o = 16; o; o >>= 1) {
        d0 += __shfl_xor_sync(0xffffffffu, d0, o);
        d1 += __shfl_xor_sync(0xffffffffu, d1, o);
        d2 += __shfl_xor_sync(0xffffffffu, d2, o);
        d3 += __shfl_xor_sync(0xffffffffu, d3, o);
    }

    const float rD = 1.f / DD;
    float mR1 = (S1.x + S2.z) * rD;
    float mI1 = (S1.y + S2.w) * rD;
    float mR2 = (S1.w + S2.y) * rD;
    float mI2 = (S1.z + S2.x) * rD;
    float qR1 = Q1.x + Q2.z + 2.f * d0;
    float qI1 = Q1.y + Q2.w + 2.f * d1;
    float qR2 = Q1.w + Q2.y + 2.f * d2;
    float qI2 = Q1.z + Q2.x + 2.f * d3;
    float vR1 = rsqrtf(fmaf(-mR1, mR1, qR1 * rD) + 1e-5f);
    float vI1 = rsqrtf(fmaf(-mI1, mI1, qI1 * rD) + 1e-5f);
    float vR2 = rsqrtf(fmaf(-mR2, mR2, qR2 * rD) + 1e-5f);
    float vI2 = rsqrtf(fmaf(-mI2, mI2, qI2 * rD) + 1e-5f);

    // normalize + complex multiply + partials, all lane-local
    const float4* wp = reinterpret_cast<const float4*>(wABf) + ((size_t)rr << 7);
    float s2A = 0.f, s2B = 0.f, q2A = 0.f, q2B = 0.f, dA = 0.f, dB = 0.f;
#pragma unroll
    for (int h = 0; h < 2; ++h) {
        int o = lane + h * 32;
        float4 wa = wp[o];
        float4 wb = wp[64 + o];
#pragma unroll
        for (int c = 0; c < 4; ++c) {
            float r1 = ((&R1[h].x)[c] - mR1) * vR1;
            float i1v = ((&I1[h].x)[c] - mI1) * vI1;
            float r2 = ((&R2[h].x)[c] - mR2) * vR2;
            float i2v = ((&I2[h].x)[c] - mI2) * vI2;
            float rc = fmaf(r1, r2, -i1v * i2v);
            float ic = fmaf(r1, i2v, i1v * r2);
            s2A += rc;
            s2B += ic;
            q2A = fmaf(rc, rc, q2A);
            q2B = fmaf(ic, ic, q2B);
            dA = fmaf(rc, (&wa.x)[c], dA);
            dB = fmaf(ic, (&wb.x)[c], dB);
        }
    }

    // Tree B: 6 values, one butterfly
#pragma unroll
    for (int o = 16; o; o >>= 1) {
        s2A += __shfl_xor_sync(0xffffffffu, s2A, o);
        s2B += __shfl_xor_sync(0xffffffffu, s2B, o);
        q2A += __shfl_xor_sync(0xffffffffu, q2A, o);
        q2B += __shfl_xor_sync(0xffffffffu, q2B, o);
        dA  += __shfl_xor_sync(0xffffffffu, dA, o);
        dB  += __shfl_xor_sync(0xffffffffu, dB, o);
    }

    if (lane == 0) {
        float sAr = RS[rr * 2], sBr = RS[rr * 2 + 1];
        float mA = s2A * rD;
        float mB = s2B * rD;
        float invA = rsqrtf(fmaf(-mA, mA, q2A * rD) + 1e-5f);
        float invB = rsqrtf(fmaf(-mB, mB, q2B * rD) + 1e-5f);
        float acc = invA * fmaf(-mA, sAr, dA) + invB * fmaf(-mB, sBr, dB);
        out[gw] = 1.f / (1.f + expf(-acc));
    }
}

// ---------------------------------------------------------------------------
extern "C" void kernel_launch(void* const* d_in, const int* in_sizes, int n_in,
                              void* d_out, int out_size) {
    const float* drug_fp   = (const float*)d_in[0];
    const float* drug_init = (const float*)d_in[1];
    const float* x1        = (const float*)d_in[2];
    const float* x2        = (const float*)d_in[3];
    const float* W_fp      = (const float*)d_in[4];
    const float* W_skip    = (const float*)d_in[5];
    const float* wr        = (const float*)d_in[6];
    const float* wi        = (const float*)d_in[7];
    const int*   idx1      = (const int*)d_in[8];
    const int*   idx2      = (const int*)d_in[9];
    const int*   idx3      = (const int*)d_in[10];
    float*       out       = (float*)d_out;
    int E = in_sizes[8];

    float *fpn, *P, *wAB, *NS, *RS;
    cudaGetSymbolAddress((void**)&fpn, g_fpn);
    cudaGetSymbolAddress((void**)&P,   g_P);
    cudaGetSymbolAddress((void**)&wAB, g_wAB);
    cudaGetSymbolAddress((void**)&NS,  g_NS);
    cudaGetSymbolAddress((void**)&RS,  g_RS);

    // 1) fp_n = elu(LN(drug_fp))
    lnelu512_kernel<<<(NN * 32 + 255) / 256, 256>>>(drug_fp, fpn);

    // 2) pack x1/x2 and relation weights
    pack_kernel<<<(NN * DD + 255) / 256, 256>>>(x1, x2, wr, wi, P, wAB);

    // 3) GEMMs -> slots 2/3 of P
    dim3 gg((NN + 63) / 64, DD / 64, 2);
    gemm_nt_kernel<<<gg, 256>>>(fpn, W_fp, drug_init, W_skip, P);

    // 4) per-node and per-relation stats
    nodestat_kernel<<<(NN * 32 + 255) / 256, 256>>>(P, NS);
    relstat_kernel<<<(RR * 32 + 255) / 256, 256>>>(wAB, RS);

    // 5) edge phase: one warp per edge
    edge_kernel<<<(E + 7) / 8, 256>>>(P, wAB, NS, RS, idx1, idx2, idx3, out, E);
}

// round 7
// speedup vs baseline: 1.3904x; 1.0705x over previous
#include <cuda_runtime.h>
#include <cuda_fp16.h>
#include <math.h>

#define NN 2000   // nodes
#define HH 512    // hidden
#define DD 256    // embed dim
#define RR 86     // relations

// Scratch
__device__ float  g_fpn[NN * HH];
__device__ __half g_P[NN * 4 * DD];     // per node: [x1 | x2 | xfp | xskip] (fp16)
__device__ __half g_wAB[RR * 2 * DD];   // per relation: [wr-wi | wr+wi] (fp16)
__device__ float  g_NS[NN * 8];         // per node: S[4], Q[4] (stats of the fp16 values)
__device__ float  g_RS[RR * 2];         // per relation: sum(wA), sum(wB)

__device__ __forceinline__ float elu1(float x) {
    return x > 0.f ? x : expm1f(x);
}
__device__ __forceinline__ float sum4(const float4& v) {
    return (v.x + v.y) + (v.z + v.w);
}
__device__ __forceinline__ float sq4(const float4& v) {
    float q = v.x * v.x;
    q = fmaf(v.y, v.y, q);
    q = fmaf(v.z, v.z, q);
    q = fmaf(v.w, v.w, q);
    return q;
}
// convert a float4-load of 8 halves into 8 floats
__device__ __forceinline__ void cvt8(const float4& r, float* f) {
    const __half2* h = reinterpret_cast<const __half2*>(&r);
#pragma unroll
    for (int i = 0; i < 4; ++i) {
        float2 t = __half22float2(h[i]);
        f[2 * i]     = t.x;
        f[2 * i + 1] = t.y;
    }
}

// ---------------------------------------------------------------------------
// Kernel 1: fp_n = elu(LayerNorm(drug_fp)), one warp per row (H=512)
// ---------------------------------------------------------------------------
__global__ void lnelu512_kernel(const float* __restrict__ in, float* __restrict__ out) {
    int gw   = (blockIdx.x * blockDim.x + threadIdx.x) >> 5;
    int lane = threadIdx.x & 31;
    if (gw >= NN) return;
    const float4* p = reinterpret_cast<const float4*>(in + (size_t)gw * HH);
    float4 v[4];
    float s = 0.f, q = 0.f;
#pragma unroll
    for (int i = 0; i < 4; ++i) {
        v[i] = p[lane + 32 * i];
        s += sum4(v[i]);
        q += sq4(v[i]);
    }
#pragma unroll
    for (int o = 16; o; o >>= 1) {
        s += __shfl_xor_sync(0xffffffffu, s, o);
        q += __shfl_xor_sync(0xffffffffu, q, o);
    }
    float m   = s * (1.f / HH);
    float var = fmaf(-m, m, q * (1.f / HH));
    float inv = rsqrtf(var + 1e-5f);
    float4* o4 = reinterpret_cast<float4*>(out + (size_t)gw * HH);
#pragma unroll
    for (int i = 0; i < 4; ++i) {
        float4 y;
        y.x = elu1((v[i].x - m) * inv);
        y.y = elu1((v[i].y - m) * inv);
        y.z = elu1((v[i].z - m) * inv);
        y.w = elu1((v[i].w - m) * inv);
        o4[lane + 32 * i] = y;
    }
}

// ---------------------------------------------------------------------------
// Kernel 2: pack x1/x2 into P (fp16), precombine relation weights (fp16)
// ---------------------------------------------------------------------------
__global__ void pack_kernel(const float* __restrict__ x1, const float* __restrict__ x2,
                            const float* __restrict__ wr, const float* __restrict__ wi,
                            __half* __restrict__ P, __half* __restrict__ wAB) {
    int i = blockIdx.x * blockDim.x + threadIdx.x;
    if (i < NN * DD) {
        int n = i >> 8, d = i & 255;
        P[(size_t)n * (4 * DD) + d]      = __float2half(x1[i]);
        P[(size_t)n * (4 * DD) + DD + d] = __float2half(x2[i]);
    }
    if (i < RR * DD) {
        int r = i >> 8, d = i & 255;
        float a = wr[i], b = wi[i];
        wAB[(size_t)r * (2 * DD) + d]      = __float2half(a - b);
        wAB[(size_t)r * (2 * DD) + DD + d] = __float2half(a + b);
    }
}

// ---------------------------------------------------------------------------
// Kernel 3: GEMM C[n,slot,d] = (elu?)(sum_h A[n,h] * W[d,h]) -> fp16 into P
// ---------------------------------------------------------------------------
__global__ void __launch_bounds__(256)
gemm_nt_kernel(const float* __restrict__ A0, const float* __restrict__ W0,
               const float* __restrict__ A1, const float* __restrict__ W1,
               __half* __restrict__ P) {
    __shared__ float As[16][65];
    __shared__ float Ws[16][65];
    const float* A = blockIdx.z ? A1 : A0;
    const float* W = blockIdx.z ? W1 : W0;
    int slot = blockIdx.z ? 3 : 2;
    int doElu = blockIdx.z ? 0 : 1;
    int tid = threadIdx.x;
    int tx = tid & 15, ty = tid >> 4;
    int n0 = blockIdx.x * 64, d0 = blockIdx.y * 64;
    float acc[4][4] = {};
    for (int h0 = 0; h0 < HH; h0 += 16) {
#pragma unroll
        for (int i = 0; i < 4; ++i) {
            int idx = tid + i * 256;
            int k = idx & 15, n = idx >> 4;
            int gn = n0 + n;
            As[k][n] = (gn < NN) ? A[(size_t)gn * HH + h0 + k] : 0.f;
            Ws[k][n] = W[(size_t)(d0 + n) * HH + h0 + k];
        }
        __syncthreads();
#pragma unroll
        for (int k = 0; k < 16; ++k) {
            float a[4], b[4];
#pragma unroll
            for (int i = 0; i < 4; ++i) a[i] = As[k][ty + 16 * i];
#pragma unroll
            for (int j = 0; j < 4; ++j) b[j] = Ws[k][tx + 16 * j];
#pragma unroll
            for (int i = 0; i < 4; ++i)
#pragma unroll
                for (int j = 0; j < 4; ++j)
                    acc[i][j] = fmaf(a[i], b[j], acc[i][j]);
        }
        __syncthreads();
    }
#pragma unroll
    for (int i = 0; i < 4; ++i) {
        int n = n0 + ty + 16 * i;
        if (n >= NN) continue;
#pragma unroll
        for (int j = 0; j < 4; ++j) {
            float v = acc[i][j];
            if (doElu) v = elu1(v);
            P[(size_t)n * (4 * DD) + slot * DD + d0 + tx + 16 * j] = __float2half(v);
        }
    }
}

// ---------------------------------------------------------------------------
// Kernel 4: per-node stats of the fp16 values. One warp per node.
// ---------------------------------------------------------------------------
__global__ void nodestat_kernel(const __half* __restrict__ P, float* __restrict__ NS) {
    int gw   = (blockIdx.x * blockDim.x + threadIdx.x) >> 5;
    int lane = threadIdx.x & 31;
    if (gw >= NN) return;
    // node = 1024 halves = 128 float4 units; slot = 32 units
    const float4* p = reinterpret_cast<const float4*>(P) + ((size_t)gw << 7);
    float s[4], q[4];
#pragma unroll
    for (int k = 0; k < 4; ++k) {
        float f[8];
        cvt8(p[k * 32 + lane], f);
        float ss = 0.f, qq = 0.f;
#pragma unroll
        for (int j = 0; j < 8; ++j) {
            ss += f[j];
            qq = fmaf(f[j], f[j], qq);
        }
        s[k] = ss;
        q[k] = qq;
    }
#pragma unroll
    for (int o = 16; o; o >>= 1) {
#pragma unroll
        for (int k = 0; k < 4; ++k) {
            s[k] += __shfl_xor_sync(0xffffffffu, s[k], o);
            q[k] += __shfl_xor_sync(0xffffffffu, q[k], o);
        }
    }
    if (lane == 0) {
#pragma unroll
        for (int k = 0; k < 4; ++k) {
            NS[gw * 8 + k]     = s[k];
            NS[gw * 8 + 4 + k] = q[k];
        }
    }
}

// ---------------------------------------------------------------------------
// Kernel 5: per-relation weight sums (of the fp16 values). One warp per relation.
// ---------------------------------------------------------------------------
__global__ void relstat_kernel(const __half* __restrict__ wAB, float* __restrict__ RS) {
    int gw   = (blockIdx.x * blockDim.x + threadIdx.x) >> 5;
    int lane = threadIdx.x & 31;
    if (gw >= RR) return;
    // relation = 512 halves = 64 float4 units; wA = first 32, wB = next 32
    const float4* p = reinterpret_cast<const float4*>(wAB) + ((size_t)gw << 6);
    float fa[8], fb[8];
    cvt8(p[lane], fa);
    cvt8(p[32 + lane], fb);
    float sA = 0.f, sB = 0.f;
#pragma unroll
    for (int j = 0; j < 8; ++j) {
        sA += fa[j];
        sB += fb[j];
    }
#pragma unroll
    for (int o = 16; o; o >>= 1) {
        sA += __shfl_xor_sync(0xffffffffu, sA, o);
        sB += __shfl_xor_sync(0xffffffffu, sB, o);
    }
    if (lane == 0) {
        RS[gw * 2]     = sA;
        RS[gw * 2 + 1] = sB;
    }
}

// ---------------------------------------------------------------------------
// Kernel 6: edge phase. One warp per edge; lane owns 8 elems.
// 8 LDG.128 node gathers (fp16) + 2 weight loads. Two shuffle trees.
// ---------------------------------------------------------------------------
__global__ void __launch_bounds__(256, 4)
edge_kernel(const __half* __restrict__ Ph, const __half* __restrict__ wABh,
            const float* __restrict__ NS, const float* __restrict__ RS,
            const int* __restrict__ idx1, const int* __restrict__ idx2,
            const int* __restrict__ idx3,
            float* __restrict__ out, int E) {
    int gw = (blockIdx.x * blockDim.x + threadIdx.x) >> 5;
    if (gw >= E) return;
    int lane = threadIdx.x & 31;

    int i1 = idx1[gw], i2 = idx2[gw], rr = idx3[gw];
    const float4* p1 = reinterpret_cast<const float4*>(Ph) + ((size_t)i1 << 7);
    const float4* p2 = reinterpret_cast<const float4*>(Ph) + ((size_t)i2 << 7);
    const float4* wp = reinterpret_cast<const float4*>(wABh) + ((size_t)rr << 6);

    // Issue all raw loads up front (MLP): 8 node rows + 2 weight rows
    float4 ra0 = p1[lane];           // x1[i1]
    float4 ra1 = p1[32 + lane];      // x2[i1]
    float4 ra2 = p1[64 + lane];      // xfp[i1]
    float4 ra3 = p1[96 + lane];      // xskip[i1]
    float4 rb0 = p2[lane];           // x1[i2]
    float4 rb1 = p2[32 + lane];      // x2[i2]
    float4 rb2 = p2[64 + lane];      // xfp[i2]
    float4 rb3 = p2[96 + lane];      // xskip[i2]
    float4 rwa = wp[lane];           // wA
    float4 rwb = wp[32 + lane];      // wB

    // node stats (broadcast loads, L1-resident)
    const float4* ns1 = reinterpret_cast<const float4*>(NS + i1 * 8);
    const float4* ns2 = reinterpret_cast<const float4*>(NS + i2 * 8);
    float4 S1 = ns1[0], Q1 = ns1[1];
    float4 S2 = ns2[0], Q2 = ns2[1];

    float A0[8], A1[8], A2[8], A3[8], B0[8], B1[8], B2[8], B3[8];
    cvt8(ra0, A0); cvt8(ra1, A1); cvt8(ra2, A2); cvt8(ra3, A3);
    cvt8(rb0, B0); cvt8(rb1, B1); cvt8(rb2, B2); cvt8(rb3, B3);

    // R1 = x1[i1]+xfp[i2], I1 = x2[i1]+xskip[i2], R2 = xskip[i1]+x2[i2], I2 = xfp[i1]+x1[i2]
    float R1[8], I1[8], R2[8], I2[8];
    float d0 = 0.f, d1 = 0.f, d2 = 0.f, d3 = 0.f;
#pragma unroll
    for (int j = 0; j < 8; ++j) {
        R1[j] = A0[j] + B2[j];
        I1[j] = A1[j] + B3[j];
        R2[j] = A3[j] + B1[j];
        I2[j] = A2[j] + B0[j];
        d0 = fmaf(A0[j], B2[j], d0);
        d1 = fmaf(A1[j], B3[j], d1);
        d2 = fmaf(A3[j], B1[j], d2);
        d3 = fmaf(A2[j], B0[j], d3);
    }

    // Tree A: reduce the 4 cross dots
#pragma unroll
    for (int o = 16; o; o >>= 1) {
        d0 += __shfl_xor_sync(0xffffffffu, d0, o);
        d1 += __shfl_xor_sync(0xffffffffu, d1, o);
        d2 += __shfl_xor_sync(0xffffffffu, d2, o);
        d3 += __shfl_xor_sync(0xffffffffu, d3, o);
    }

    const float rD = 1.f / DD;
    float mR1 = (S1.x + S2.z) * rD;
    float mI1 = (S1.y + S2.w) * rD;
    float mR2 = (S1.w + S2.y) * rD;
    float mI2 = (S1.z + S2.x) * rD;
    float qR1 = Q1.x + Q2.z + 2.f * d0;
    float qI1 = Q1.y + Q2.w + 2.f * d1;
    float qR2 = Q1.w + Q2.y + 2.f * d2;
    float qI2 = Q1.z + Q2.x + 2.f * d3;
    float vR1 = rsqrtf(fmaf(-mR1, mR1, qR1 * rD) + 1e-5f);
    float vI1 = rsqrtf(fmaf(-mI1, mI1, qI1 * rD) + 1e-5f);
    float vR2 = rsqrtf(fmaf(-mR2, mR2, qR2 * rD) + 1e-5f);
    float vI2 = rsqrtf(fmaf(-mI2, mI2, qI2 * rD) + 1e-5f);

    float wa[8], wb[8];
    cvt8(rwa, wa); cvt8(rwb, wb);

    float s2A = 0.f, s2B = 0.f, q2A = 0.f, q2B = 0.f, dA = 0.f, dB = 0.f;
#pragma unroll
    for (int j = 0; j < 8; ++j) {
        float r1 = (R1[j] - mR1) * vR1;
        float i1v = (I1[j] - mI1) * vI1;
        float r2 = (R2[j] - mR2) * vR2;
        float i2v = (I2[j] - mI2) * vI2;
        float rc = fmaf(r1, r2, -i1v * i2v);
        float ic = fmaf(r1, i2v, i1v * r2);
        s2A += rc;
        s2B += ic;
        q2A = fmaf(rc, rc, q2A);
        q2B = fmaf(ic, ic, q2B);
        dA = fmaf(rc, wa[j], dA);
        dB = fmaf(ic, wb[j], dB);
    }

    // Tree B: 6 values, one butterfly
#pragma unroll
    for (int o = 16; o; o >>= 1) {
        s2A += __shfl_xor_sync(0xffffffffu, s2A, o);
        s2B += __shfl_xor_sync(0xffffffffu, s2B, o);
        q2A += __shfl_xor_sync(0xffffffffu, q2A, o);
        q2B += __shfl_xor_sync(0xffffffffu, q2B, o);
        dA  += __shfl_xor_sync(0xffffffffu, dA, o);
        dB  += __shfl_xor_sync(0xffffffffu, dB, o);
    }

    if (lane == 0) {
        float sAr = RS[rr * 2], sBr = RS[rr * 2 + 1];
        float mA = s2A * rD;
        float mB = s2B * rD;
        float invA = rsqrtf(fmaf(-mA, mA, q2A * rD) + 1e-5f);
        float invB = rsqrtf(fmaf(-mB, mB, q2B * rD) + 1e-5f);
        float acc = invA * fmaf(-mA, sAr, dA) + invB * fmaf(-mB, sBr, dB);
        out[gw] = 1.f / (1.f + expf(-acc));
    }
}

// ---------------------------------------------------------------------------
extern "C" void kernel_launch(void* const* d_in, const int* in_sizes, int n_in,
                              void* d_out, int out_size) {
    const float* drug_fp   = (const float*)d_in[0];
    const float* drug_init = (const float*)d_in[1];
    const float* x1        = (const float*)d_in[2];
    const float* x2        = (const float*)d_in[3];
    const float* W_fp      = (const float*)d_in[4];
    const float* W_skip    = (const float*)d_in[5];
    const float* wr        = (const float*)d_in[6];
    const float* wi        = (const float*)d_in[7];
    const int*   idx1      = (const int*)d_in[8];
    const int*   idx2      = (const int*)d_in[9];
    const int*   idx3      = (const int*)d_in[10];
    float*       out       = (float*)d_out;
    int E = in_sizes[8];

    float *fpn, *NS, *RS;
    __half *P, *wAB;
    cudaGetSymbolAddress((void**)&fpn, g_fpn);
    cudaGetSymbolAddress((void**)&P,   g_P);
    cudaGetSymbolAddress((void**)&wAB, g_wAB);
    cudaGetSymbolAddress((void**)&NS,  g_NS);
    cudaGetSymbolAddress((void**)&RS,  g_RS);

    // 1) fp_n = elu(LN(drug_fp))
    lnelu512_kernel<<<(NN * 32 + 255) / 256, 256>>>(drug_fp, fpn);

    // 2) pack x1/x2 and relation weights (fp16)
    pack_kernel<<<(NN * DD + 255) / 256, 256>>>(x1, x2, wr, wi, P, wAB);

    // 3) GEMMs -> slots 2/3 of P (fp16)
    dim3 gg((NN + 63) / 64, DD / 64, 2);
    gemm_nt_kernel<<<gg, 256>>>(fpn, W_fp, drug_init, W_skip, P);

    // 4) per-node and per-relation stats (of the fp16 values)
    nodestat_kernel<<<(NN * 32 + 255) / 256, 256>>>(P, NS);
    relstat_kernel<<<(RR * 32 + 255) / 256, 256>>>(wAB, RS);

    // 5) edge phase: one warp per edge
    edge_kernel<<<(E + 7) / 8, 256>>>(P, wAB, NS, RS, idx1, idx2, idx3, out, E);
}

// round 9
// speedup vs baseline: 1.5156x; 1.0900x over previous
#include <cuda_runtime.h>
#include <cuda_fp16.h>
#include <math.h>

#define NN 2000   // nodes
#define HH 512    // hidden
#define DD 256    // embed dim
#define RR 86     // relations

// Scratch
__device__ float  g_fpn[NN * HH];
__device__ __half g_P[NN * 4 * DD];     // per node: [x1 | x2 | xfp | xskip] (fp16)
__device__ __half g_wAB[RR * 2 * DD];   // per relation: [wr-wi | wr+wi] (fp16)
__device__ float  g_NS[NN * 8];         // per node: S[4] (sums of fp16 values); Q unused
__device__ float  g_RS[RR * 2];         // per relation: sum(wA), sum(wB)

__device__ __forceinline__ float elu1(float x) {
    return x > 0.f ? x : expm1f(x);
}
__device__ __forceinline__ float sum4(const float4& v) {
    return (v.x + v.y) + (v.z + v.w);
}
__device__ __forceinline__ float sq4(const float4& v) {
    float q = v.x * v.x;
    q = fmaf(v.y, v.y, q);
    q = fmaf(v.z, v.z, q);
    q = fmaf(v.w, v.w, q);
    return q;
}
// convert a float4-load of 8 halves into 8 floats
__device__ __forceinline__ void cvt8(const float4& r, float* f) {
    const __half2* h = reinterpret_cast<const __half2*>(&r);
#pragma unroll
    for (int i = 0; i < 4; ++i) {
        float2 t = __half22float2(h[i]);
        f[2 * i]     = t.x;
        f[2 * i + 1] = t.y;
    }
}

// ---------------------------------------------------------------------------
// Kernel 1: fp_n = elu(LayerNorm(drug_fp)), one warp per row (H=512)
// ---------------------------------------------------------------------------
__global__ void lnelu512_kernel(const float* __restrict__ in, float* __restrict__ out) {
    int gw   = (blockIdx.x * blockDim.x + threadIdx.x) >> 5;
    int lane = threadIdx.x & 31;
    if (gw >= NN) return;
    const float4* p = reinterpret_cast<const float4*>(in + (size_t)gw * HH);
    float4 v[4];
    float s = 0.f, q = 0.f;
#pragma unroll
    for (int i = 0; i < 4; ++i) {
        v[i] = p[lane + 32 * i];
        s += sum4(v[i]);
        q += sq4(v[i]);
    }
#pragma unroll
    for (int o = 16; o; o >>= 1) {
        s += __shfl_xor_sync(0xffffffffu, s, o);
        q += __shfl_xor_sync(0xffffffffu, q, o);
    }
    float m   = s * (1.f / HH);
    float var = fmaf(-m, m, q * (1.f / HH));
    float inv = rsqrtf(var + 1e-5f);
    float4* o4 = reinterpret_cast<float4*>(out + (size_t)gw * HH);
#pragma unroll
    for (int i = 0; i < 4; ++i) {
        float4 y;
        y.x = elu1((v[i].x - m) * inv);
        y.y = elu1((v[i].y - m) * inv);
        y.z = elu1((v[i].z - m) * inv);
        y.w = elu1((v[i].w - m) * inv);
        o4[lane + 32 * i] = y;
    }
}

// ---------------------------------------------------------------------------
// Kernel 2: pack x1/x2 into P (fp16), precombine relation weights (fp16)
// ---------------------------------------------------------------------------
__global__ void pack_kernel(const float* __restrict__ x1, const float* __restrict__ x2,
                            const float* __restrict__ wr, const float* __restrict__ wi,
                            __half* __restrict__ P, __half* __restrict__ wAB) {
    int i = blockIdx.x * blockDim.x + threadIdx.x;
    if (i < NN * DD) {
        int n = i >> 8, d = i & 255;
        P[(size_t)n * (4 * DD) + d]      = __float2half(x1[i]);
        P[(size_t)n * (4 * DD) + DD + d] = __float2half(x2[i]);
    }
    if (i < RR * DD) {
        int r = i >> 8, d = i & 255;
        float a = wr[i], b = wi[i];
        wAB[(size_t)r * (2 * DD) + d]      = __float2half(a - b);
        wAB[(size_t)r * (2 * DD) + DD + d] = __float2half(a + b);
    }
}

// ---------------------------------------------------------------------------
// Kernel 3: GEMM C[n,slot,d] = (elu?)(sum_h A[n,h] * W[d,h]) -> fp16 into P
// ---------------------------------------------------------------------------
__global__ void __launch_bounds__(256)
gemm_nt_kernel(const float* __restrict__ A0, const float* __restrict__ W0,
               const float* __restrict__ A1, const float* __restrict__ W1,
               __half* __restrict__ P) {
    __shared__ float As[16][65];
    __shared__ float Ws[16][65];
    const float* A = blockIdx.z ? A1 : A0;
    const float* W = blockIdx.z ? W1 : W0;
    int slot = blockIdx.z ? 3 : 2;
    int doElu = blockIdx.z ? 0 : 1;
    int tid = threadIdx.x;
    int tx = tid & 15, ty = tid >> 4;
    int n0 = blockIdx.x * 64, d0 = blockIdx.y * 64;
    float acc[4][4] = {};
    for (int h0 = 0; h0 < HH; h0 += 16) {
#pragma unroll
        for (int i = 0; i < 4; ++i) {
            int idx = tid + i * 256;
            int k = idx & 15, n = idx >> 4;
            int gn = n0 + n;
            As[k][n] = (gn < NN) ? A[(size_t)gn * HH + h0 + k] : 0.f;
            Ws[k][n] = W[(size_t)(d0 + n) * HH + h0 + k];
        }
        __syncthreads();
#pragma unroll
        for (int k = 0; k < 16; ++k) {
            float a[4], b[4];
#pragma unroll
            for (int i = 0; i < 4; ++i) a[i] = As[k][ty + 16 * i];
#pragma unroll
            for (int j = 0; j < 4; ++j) b[j] = Ws[k][tx + 16 * j];
#pragma unroll
            for (int i = 0; i < 4; ++i)
#pragma unroll
                for (int j = 0; j < 4; ++j)
                    acc[i][j] = fmaf(a[i], b[j], acc[i][j]);
        }
        __syncthreads();
    }
#pragma unroll
    for (int i = 0; i < 4; ++i) {
        int n = n0 + ty + 16 * i;
        if (n >= NN) continue;
#pragma unroll
        for (int j = 0; j < 4; ++j) {
            float v = acc[i][j];
            if (doElu) v = elu1(v);
            P[(size_t)n * (4 * DD) + slot * DD + d0 + tx + 16 * j] = __float2half(v);
        }
    }
}

// ---------------------------------------------------------------------------
// Kernel 4: per-node sums of the fp16 values. One warp per node.
// (Only S needed now; variance comes from per-edge sumsq of combined vectors.)
// ---------------------------------------------------------------------------
__global__ void nodestat_kernel(const __half* __restrict__ P, float* __restrict__ NS) {
    int gw   = (blockIdx.x * blockDim.x + threadIdx.x) >> 5;
    int lane = threadIdx.x & 31;
    if (gw >= NN) return;
    const float4* p = reinterpret_cast<const float4*>(P) + ((size_t)gw << 7);
    float s[4];
#pragma unroll
    for (int k = 0; k < 4; ++k) {
        float f[8];
        cvt8(p[k * 32 + lane], f);
        float ss = 0.f;
#pragma unroll
        for (int j = 0; j < 8; ++j) ss += f[j];
        s[k] = ss;
    }
#pragma unroll
    for (int o = 16; o; o >>= 1) {
#pragma unroll
        for (int k = 0; k < 4; ++k)
            s[k] += __shfl_xor_sync(0xffffffffu, s[k], o);
    }
    if (lane == 0) {
#pragma unroll
        for (int k = 0; k < 4; ++k) NS[gw * 8 + k] = s[k];
    }
}

// ---------------------------------------------------------------------------
// Kernel 5: per-relation weight sums (of the fp16 values). One warp per relation.
// ---------------------------------------------------------------------------
__global__ void relstat_kernel(const __half* __restrict__ wAB, float* __restrict__ RS) {
    int gw   = (blockIdx.x * blockDim.x + threadIdx.x) >> 5;
    int lane = threadIdx.x & 31;
    if (gw >= RR) return;
    const float4* p = reinterpret_cast<const float4*>(wAB) + ((size_t)gw << 6);
    float fa[8], fb[8];
    cvt8(p[lane], fa);
    cvt8(p[32 + lane], fb);
    float sA = 0.f, sB = 0.f;
#pragma unroll
    for (int j = 0; j < 8; ++j) {
        sA += fa[j];
        sB += fb[j];
    }
#pragma unroll
    for (int o = 16; o; o >>= 1) {
        sA += __shfl_xor_sync(0xffffffffu, sA, o);
        sB += __shfl_xor_sync(0xffffffffu, sB, o);
    }
    if (lane == 0) {
        RS[gw * 2]     = sA;
        RS[gw * 2 + 1] = sB;
    }
}

// ---------------------------------------------------------------------------
// Kernel 6: edge phase. One warp per edge; lane owns 8 elems.
// HADD2 combine, variance from per-edge sumsq, FMA-form normalize.
// ---------------------------------------------------------------------------
__device__ __forceinline__ __half2 h2(const float4& r, int k) {
    return reinterpret_cast<const __half2*>(&r)[k];
}

__global__ void __launch_bounds__(256, 4)
edge_kernel(const __half* __restrict__ Ph, const __half* __restrict__ wABh,
            const float* __restrict__ NS, const float* __restrict__ RS,
            const int* __restrict__ idx1, const int* __restrict__ idx2,
            const int* __restrict__ idx3,
            float* __restrict__ out, int E) {
    int gw = (blockIdx.x * blockDim.x + threadIdx.x) >> 5;
    if (gw >= E) return;
    int lane = threadIdx.x & 31;

    int i1 = idx1[gw], i2 = idx2[gw], rr = idx3[gw];
    const float4* p1 = reinterpret_cast<const float4*>(Ph) + ((size_t)i1 << 7);
    const float4* p2 = reinterpret_cast<const float4*>(Ph) + ((size_t)i2 << 7);
    const float4* wp = reinterpret_cast<const float4*>(wABh) + ((size_t)rr << 6);

    // Raw loads up front (MLP): 8 node rows + 2 weight rows
    float4 ra0 = p1[lane];           // x1[i1]
    float4 ra1 = p1[32 + lane];      // x2[i1]
    float4 ra2 = p1[64 + lane];      // xfp[i1]
    float4 ra3 = p1[96 + lane];      // xskip[i1]
    float4 rb0 = p2[lane];           // x1[i2]
    float4 rb1 = p2[32 + lane];      // x2[i2]
    float4 rb2 = p2[64 + lane];      // xfp[i2]
    float4 rb3 = p2[96 + lane];      // xskip[i2]
    float4 rwa = wp[lane];           // wA
    float4 rwb = wp[32 + lane];      // wB

    // node sums (broadcast loads, L1-resident)
    float4 S1 = *reinterpret_cast<const float4*>(NS + i1 * 8);
    float4 S2 = *reinterpret_cast<const float4*>(NS + i2 * 8);

    // Combine in half2: R1 = x1[i1]+xfp[i2], I1 = x2[i1]+xskip[i2],
    //                   R2 = xskip[i1]+x2[i2], I2 = xfp[i1]+x1[i2]
    float R1[8], I1[8], R2[8], I2[8];
    float qR1 = 0.f, qI1 = 0.f, qR2 = 0.f, qI2 = 0.f;
#pragma unroll
    for (int k = 0; k < 4; ++k) {
        float2 t;
        t = __half22float2(__hadd2(h2(ra0, k), h2(rb2, k)));
        R1[2 * k] = t.x; R1[2 * k + 1] = t.y;
        qR1 = fmaf(t.x, t.x, qR1); qR1 = fmaf(t.y, t.y, qR1);
        t = __half22float2(__hadd2(h2(ra1, k), h2(rb3, k)));
        I1[2 * k] = t.x; I1[2 * k + 1] = t.y;
        qI1 = fmaf(t.x, t.x, qI1); qI1 = fmaf(t.y, t.y, qI1);
        t = __half22float2(__hadd2(h2(ra3, k), h2(rb1, k)));
        R2[2 * k] = t.x; R2[2 * k + 1] = t.y;
        qR2 = fmaf(t.x, t.x, qR2); qR2 = fmaf(t.y, t.y, qR2);
        t = __half22float2(__hadd2(h2(ra2, k), h2(rb0, k)));
        I2[2 * k] = t.x; I2[2 * k + 1] = t.y;
        qI2 = fmaf(t.x, t.x, qI2); qI2 = fmaf(t.y, t.y, qI2);
    }

    // Tree A: reduce the 4 sumsq values
#pragma unroll
    for (int o = 16; o; o >>= 1) {
        qR1 += __shfl_xor_sync(0xffffffffu, qR1, o);
        qI1 += __shfl_xor_sync(0xffffffffu, qI1, o);
        qR2 += __shfl_xor_sync(0xffffffffu, qR2, o);
        qI2 += __shfl_xor_sync(0xffffffffu, qI2, o);
    }

    const float rD = 1.f / DD;
    float mR1 = (S1.x + S2.z) * rD;
    float mI1 = (S1.y + S2.w) * rD;
    float mR2 = (S1.w + S2.y) * rD;
    float mI2 = (S1.z + S2.x) * rD;
    float vR1 = rsqrtf(fmaf(-mR1, mR1, qR1 * rD) + 1e-5f);
    float vI1 = rsqrtf(fmaf(-mI1, mI1, qI1 * rD) + 1e-5f);
    float vR2 = rsqrtf(fmaf(-mR2, mR2, qR2 * rD) + 1e-5f);
    float vI2 = rsqrtf(fmaf(-mI2, mI2, qI2 * rD) + 1e-5f);
    // FMA-form normalize constants
    float nR1 = -mR1 * vR1, nI1 = -mI1 * vI1, nR2 = -mR2 * vR2, nI2 = -mI2 * vI2;

    float wa[8], wb[8];
    cvt8(rwa, wa); cvt8(rwb, wb);

    float s2A = 0.f, s2B = 0.f, q2A = 0.f, q2B = 0.f, dA = 0.f, dB = 0.f;
#pragma unroll
    for (int j = 0; j < 8; ++j) {
        float r1  = fmaf(R1[j], vR1, nR1);
        float i1v = fmaf(I1[j], vI1, nI1);
        float r2  = fmaf(R2[j], vR2, nR2);
        float i2v = fmaf(I2[j], vI2, nI2);
        float rc = fmaf(r1, r2, -i1v * i2v);
        float ic = fmaf(r1, i2v, i1v * r2);
        s2A += rc;
        s2B += ic;
        q2A = fmaf(rc, rc, q2A);
        q2B = fmaf(ic, ic, q2B);
        dA = fmaf(rc, wa[j], dA);
        dB = fmaf(ic, wb[j], dB);
    }

    // Tree B: 6 values, one butterfly
#pragma unroll
    for (int o = 16; o; o >>= 1) {
        s2A += __shfl_xor_sync(0xffffffffu, s2A, o);
        s2B += __shfl_xor_sync(0xffffffffu, s2B, o);
        q2A += __shfl_xor_sync(0xffffffffu, q2A, o);
        q2B += __shfl_xor_sync(0xffffffffu, q2B, o);
        dA  += __shfl_xor_sync(0xffffffffu, dA, o);
        dB  += __shfl_xor_sync(0xffffffffu, dB, o);
    }

    if (lane == 0) {
        float sAr = RS[rr * 2], sBr = RS[rr * 2 + 1];
        float mA = s2A * rD;
        float mB = s2B * rD;
        float invA = rsqrtf(fmaf(-mA, mA, q2A * rD) + 1e-5f);
        float invB = rsqrtf(fmaf(-mB, mB, q2B * rD) + 1e-5f);
        float acc = invA * fmaf(-mA, sAr, dA) + invB * fmaf(-mB, sBr, dB);
        out[gw] = 1.f / (1.f + expf(-acc));
    }
}

// ---------------------------------------------------------------------------
extern "C" void kernel_launch(void* const* d_in, const int* in_sizes, int n_in,
                              void* d_out, int out_size) {
    const float* drug_fp   = (const float*)d_in[0];
    const float* drug_init = (const float*)d_in[1];
    const float* x1        = (const float*)d_in[2];
    const float* x2        = (const float*)d_in[3];
    const float* W_fp      = (const float*)d_in[4];
    const float* W_skip    = (const float*)d_in[5];
    const float* wr        = (const float*)d_in[6];
    const float* wi        = (const float*)d_in[7];
    const int*   idx1      = (const int*)d_in[8];
    const int*   idx2      = (const int*)d_in[9];
    const int*   idx3      = (const int*)d_in[10];
    float*       out       = (float*)d_out;
    int E = in_sizes[8];

    float *fpn, *NS, *RS;
    __half *P, *wAB;
    cudaGetSymbolAddress((void**)&fpn, g_fpn);
    cudaGetSymbolAddress((void**)&P,   g_P);
    cudaGetSymbolAddress((void**)&wAB, g_wAB);
    cudaGetSymbolAddress((void**)&NS,  g_NS);
    cudaGetSymbolAddress((void**)&RS,  g_RS);

    // 1) fp_n = elu(LN(drug_fp))
    lnelu512_kernel<<<(NN * 32 + 255) / 256, 256>>>(drug_fp, fpn);

    // 2) pack x1/x2 and relation weights (fp16)
    pack_kernel<<<(NN * DD + 255) / 256, 256>>>(x1, x2, wr, wi, P, wAB);

    // 3) GEMMs -> slots 2/3 of P (fp16)
    dim3 gg((NN + 63) / 64, DD / 64, 2);
    gemm_nt_kernel<<<gg, 256>>>(fpn, W_fp, drug_init, W_skip, P);

    // 4) per-node and per-relation sums (of the fp16 values)
    nodestat_kernel<<<(NN * 32 + 255) / 256, 256>>>(P, NS);
    relstat_kernel<<<(RR * 32 + 255) / 256, 256>>>(wAB, RS);

    // 5) edge phase: one warp per edge
    edge_kernel<<<(E + 7) / 8, 256>>>(P, wAB, NS, RS, idx1, idx2, idx3, out, E);
}

// round 10
// speedup vs baseline: 1.7931x; 1.1831x over previous
#include <cuda_runtime.h>
#include <cuda_fp16.h>
#include <math.h>

#define NN 2000   // nodes
#define HH 512    // hidden
#define DD 256    // embed dim
#define RR 86     // relations

// Scratch
__device__ float  g_fpn[NN * HH];
__device__ __half g_P[NN * 4 * DD];     // per node: [x1 | x2 | xfp | xskip] (fp16)
__device__ __half g_wAB[RR * 2 * DD];   // per relation: [wr-wi | wr+wi] (fp16)
__device__ float  g_NS[NN * 8];         // per node: S[4] (sums of fp16 values)
__device__ float  g_RS[RR * 2];         // per relation: sum(wA), sum(wB)

__device__ __forceinline__ float elu1(float x) {
    return x > 0.f ? x : expm1f(x);
}
__device__ __forceinline__ float sum4(const float4& v) {
    return (v.x + v.y) + (v.z + v.w);
}
__device__ __forceinline__ float sq4(const float4& v) {
    float q = v.x * v.x;
    q = fmaf(v.y, v.y, q);
    q = fmaf(v.z, v.z, q);
    q = fmaf(v.w, v.w, q);
    return q;
}
__device__ __forceinline__ void cvt8(const float4& r, float* f) {
    const __half2* h = reinterpret_cast<const __half2*>(&r);
#pragma unroll
    for (int i = 0; i < 4; ++i) {
        float2 t = __half22float2(h[i]);
        f[2 * i]     = t.x;
        f[2 * i + 1] = t.y;
    }
}
__device__ __forceinline__ __half2 h2(const float4& r, int k) {
    return reinterpret_cast<const __half2*>(&r)[k];
}
// combine two fp16 float4-rows into 4 half2 sums, accumulate fp32 sumsq
__device__ __forceinline__ void comb4(const float4& ra, const float4& rb,
                                      __half2* o, float& q) {
#pragma unroll
    for (int k = 0; k < 4; ++k) {
        __half2 s = __hadd2(h2(ra, k), h2(rb, k));
        o[k] = s;
        float2 t = __half22float2(s);
        q = fmaf(t.x, t.x, q);
        q = fmaf(t.y, t.y, q);
    }
}

// ---------------------------------------------------------------------------
// Kernel 1: fp_n = elu(LayerNorm(drug_fp)), one warp per row (H=512)
// ---------------------------------------------------------------------------
__global__ void lnelu512_kernel(const float* __restrict__ in, float* __restrict__ out) {
    int gw   = (blockIdx.x * blockDim.x + threadIdx.x) >> 5;
    int lane = threadIdx.x & 31;
    if (gw >= NN) return;
    const float4* p = reinterpret_cast<const float4*>(in + (size_t)gw * HH);
    float4 v[4];
    float s = 0.f, q = 0.f;
#pragma unroll
    for (int i = 0; i < 4; ++i) {
        v[i] = p[lane + 32 * i];
        s += sum4(v[i]);
        q += sq4(v[i]);
    }
#pragma unroll
    for (int o = 16; o; o >>= 1) {
        s += __shfl_xor_sync(0xffffffffu, s, o);
        q += __shfl_xor_sync(0xffffffffu, q, o);
    }
    float m   = s * (1.f / HH);
    float var = fmaf(-m, m, q * (1.f / HH));
    float inv = rsqrtf(var + 1e-5f);
    float4* o4 = reinterpret_cast<float4*>(out + (size_t)gw * HH);
#pragma unroll
    for (int i = 0; i < 4; ++i) {
        float4 y;
        y.x = elu1((v[i].x - m) * inv);
        y.y = elu1((v[i].y - m) * inv);
        y.z = elu1((v[i].z - m) * inv);
        y.w = elu1((v[i].w - m) * inv);
        o4[lane + 32 * i] = y;
    }
}

// ---------------------------------------------------------------------------
// Kernel 2: pack x1/x2 into P (fp16), precombine relation weights (fp16)
// ---------------------------------------------------------------------------
__global__ void pack_kernel(const float* __restrict__ x1, const float* __restrict__ x2,
                            const float* __restrict__ wr, const float* __restrict__ wi,
                            __half* __restrict__ P, __half* __restrict__ wAB) {
    int i = blockIdx.x * blockDim.x + threadIdx.x;
    if (i < NN * DD) {
        int n = i >> 8, d = i & 255;
        P[(size_t)n * (4 * DD) + d]      = __float2half(x1[i]);
        P[(size_t)n * (4 * DD) + DD + d] = __float2half(x2[i]);
    }
    if (i < RR * DD) {
        int r = i >> 8, d = i & 255;
        float a = wr[i], b = wi[i];
        wAB[(size_t)r * (2 * DD) + d]      = __float2half(a - b);
        wAB[(size_t)r * (2 * DD) + DD + d] = __float2half(a + b);
    }
}

// ---------------------------------------------------------------------------
// Kernel 3: GEMM C[n,slot,d] = (elu?)(sum_h A[n,h] * W[d,h]) -> fp16 into P
// ---------------------------------------------------------------------------
__global__ void __launch_bounds__(256)
gemm_nt_kernel(const float* __restrict__ A0, const float* __restrict__ W0,
               const float* __restrict__ A1, const float* __restrict__ W1,
               __half* __restrict__ P) {
    __shared__ float As[16][65];
    __shared__ float Ws[16][65];
    const float* A = blockIdx.z ? A1 : A0;
    const float* W = blockIdx.z ? W1 : W0;
    int slot = blockIdx.z ? 3 : 2;
    int doElu = blockIdx.z ? 0 : 1;
    int tid = threadIdx.x;
    int tx = tid & 15, ty = tid >> 4;
    int n0 = blockIdx.x * 64, d0 = blockIdx.y * 64;
    float acc[4][4] = {};
    for (int h0 = 0; h0 < HH; h0 += 16) {
#pragma unroll
        for (int i = 0; i < 4; ++i) {
            int idx = tid + i * 256;
            int k = idx & 15, n = idx >> 4;
            int gn = n0 + n;
            As[k][n] = (gn < NN) ? A[(size_t)gn * HH + h0 + k] : 0.f;
            Ws[k][n] = W[(size_t)(d0 + n) * HH + h0 + k];
        }
        __syncthreads();
#pragma unroll
        for (int k = 0; k < 16; ++k) {
            float a[4], b[4];
#pragma unroll
            for (int i = 0; i < 4; ++i) a[i] = As[k][ty + 16 * i];
#pragma unroll
            for (int j = 0; j < 4; ++j) b[j] = Ws[k][tx + 16 * j];
#pragma unroll
            for (int i = 0; i < 4; ++i)
#pragma unroll
                for (int j = 0; j < 4; ++j)
                    acc[i][j] = fmaf(a[i], b[j], acc[i][j]);
        }
        __syncthreads();
    }
#pragma unroll
    for (int i = 0; i < 4; ++i) {
        int n = n0 + ty + 16 * i;
        if (n >= NN) continue;
#pragma unroll
        for (int j = 0; j < 4; ++j) {
            float v = acc[i][j];
            if (doElu) v = elu1(v);
            P[(size_t)n * (4 * DD) + slot * DD + d0 + tx + 16 * j] = __float2half(v);
        }
    }
}

// ---------------------------------------------------------------------------
// Kernel 4: per-node sums of the fp16 values. One warp per node.
// ---------------------------------------------------------------------------
__global__ void nodestat_kernel(const __half* __restrict__ P, float* __restrict__ NS) {
    int gw   = (blockIdx.x * blockDim.x + threadIdx.x) >> 5;
    int lane = threadIdx.x & 31;
    if (gw >= NN) return;
    const float4* p = reinterpret_cast<const float4*>(P) + ((size_t)gw << 7);
    float s[4];
#pragma unroll
    for (int k = 0; k < 4; ++k) {
        float f[8];
        cvt8(p[k * 32 + lane], f);
        float ss = 0.f;
#pragma unroll
        for (int j = 0; j < 8; ++j) ss += f[j];
        s[k] = ss;
    }
#pragma unroll
    for (int o = 16; o; o >>= 1) {
#pragma unroll
        for (int k = 0; k < 4; ++k)
            s[k] += __shfl_xor_sync(0xffffffffu, s[k], o);
    }
    if (lane == 0) {
#pragma unroll
        for (int k = 0; k < 4; ++k) NS[gw * 8 + k] = s[k];
    }
}

// ---------------------------------------------------------------------------
// Kernel 5: per-relation weight sums. One warp per relation.
// ---------------------------------------------------------------------------
__global__ void relstat_kernel(const __half* __restrict__ wAB, float* __restrict__ RS) {
    int gw   = (blockIdx.x * blockDim.x + threadIdx.x) >> 5;
    int lane = threadIdx.x & 31;
    if (gw >= RR) return;
    const float4* p = reinterpret_cast<const float4*>(wAB) + ((size_t)gw << 6);
    float fa[8], fb[8];
    cvt8(p[lane], fa);
    cvt8(p[32 + lane], fb);
    float sA = 0.f, sB = 0.f;
#pragma unroll
    for (int j = 0; j < 8; ++j) {
        sA += fa[j];
        sB += fb[j];
    }
#pragma unroll
    for (int o = 16; o; o >>= 1) {
        sA += __shfl_xor_sync(0xffffffffu, sA, o);
        sB += __shfl_xor_sync(0xffffffffu, sB, o);
    }
    if (lane == 0) {
        RS[gw * 2]     = sA;
        RS[gw * 2 + 1] = sB;
    }
}

// ---------------------------------------------------------------------------
// Kernel 6: edge phase. TWO edges per warp, 16-lane segments.
// Shuffle trees (offsets 8/4/2/1) reduce both segments with one instruction.
// Combined vectors kept as half2 to bound registers.
// ---------------------------------------------------------------------------
__global__ void __launch_bounds__(256, 3)
edge_kernel(const __half* __restrict__ Ph, const __half* __restrict__ wABh,
            const float* __restrict__ NS, const float* __restrict__ RS,
            const int* __restrict__ idx1, const int* __restrict__ idx2,
            const int* __restrict__ idx3,
            float* __restrict__ out, int E) {
    int warp = (blockIdx.x * blockDim.x + threadIdx.x) >> 5;
    int lane = threadIdx.x & 31;
    int seg  = lane >> 4;     // 0 or 1: which edge in this warp
    int sl   = lane & 15;     // lane within segment
    int e = warp * 2 + seg;
    bool live = (e < E);
    int ec = live ? e : (E - 1);

    int i1 = idx1[ec], i2 = idx2[ec], rr = idx3[ec];
    const float4* p1 = reinterpret_cast<const float4*>(Ph) + ((size_t)i1 << 7);
    const float4* p2 = reinterpret_cast<const float4*>(Ph) + ((size_t)i2 << 7);
    const float4* wp = reinterpret_cast<const float4*>(wABh) + ((size_t)rr << 6);

    // node sums (broadcast within segment, L1-resident)
    float4 S1 = *reinterpret_cast<const float4*>(NS + i1 * 8);
    float4 S2 = *reinterpret_cast<const float4*>(NS + i2 * 8);

    // Each segment lane covers float4 indices {sl, sl+16} of each 32-float4 row.
    // Wave 1: R1 = x1[i1]+xfp[i2], I1 = x2[i1]+xskip[i2]
    __half2 R1h[8], I1h[8], R2h[8], I2h[8];
    float qR1 = 0.f, qI1 = 0.f, qR2 = 0.f, qI2 = 0.f;
    {
        float4 a0l = p1[sl],        a0h = p1[16 + sl];     // x1[i1]
        float4 b2l = p2[64 + sl],   b2h = p2[80 + sl];     // xfp[i2]
        float4 a1l = p1[32 + sl],   a1h = p1[48 + sl];     // x2[i1]
        float4 b3l = p2[96 + sl],   b3h = p2[112 + sl];    // xskip[i2]
        comb4(a0l, b2l, R1h,     qR1);
        comb4(a0h, b2h, R1h + 4, qR1);
        comb4(a1l, b3l, I1h,     qI1);
        comb4(a1h, b3h, I1h + 4, qI1);
    }
    // Wave 2: R2 = xskip[i1]+x2[i2], I2 = xfp[i1]+x1[i2]
    {
        float4 a3l = p1[96 + sl],   a3h = p1[112 + sl];    // xskip[i1]
        float4 b1l = p2[32 + sl],   b1h = p2[48 + sl];     // x2[i2]
        float4 a2l = p1[64 + sl],   a2h = p1[80 + sl];     // xfp[i1]
        float4 b0l = p2[sl],        b0h = p2[16 + sl];     // x1[i2]
        comb4(a3l, b1l, R2h,     qR2);
        comb4(a3h, b1h, R2h + 4, qR2);
        comb4(a2l, b0l, I2h,     qI2);
        comb4(a2h, b0h, I2h + 4, qI2);
    }

    // Weight loads issued before tree A (latency hidden under the reductions)
    float4 rwal = wp[sl],      rwah = wp[16 + sl];
    float4 rwbl = wp[32 + sl], rwbh = wp[48 + sl];

    // Tree A: 4 sumsq values, 4-stage segment butterfly
#pragma unroll
    for (int o = 8; o; o >>= 1) {
        qR1 += __shfl_xor_sync(0xffffffffu, qR1, o);
        qI1 += __shfl_xor_sync(0xffffffffu, qI1, o);
        qR2 += __shfl_xor_sync(0xffffffffu, qR2, o);
        qI2 += __shfl_xor_sync(0xffffffffu, qI2, o);
    }

    const float rD = 1.f / DD;
    float mR1 = (S1.x + S2.z) * rD;
    float mI1 = (S1.y + S2.w) * rD;
    float mR2 = (S1.w + S2.y) * rD;
    float mI2 = (S1.z + S2.x) * rD;
    float vR1 = rsqrtf(fmaf(-mR1, mR1, qR1 * rD) + 1e-5f);
    float vI1 = rsqrtf(fmaf(-mI1, mI1, qI1 * rD) + 1e-5f);
    float vR2 = rsqrtf(fmaf(-mR2, mR2, qR2 * rD) + 1e-5f);
    float vI2 = rsqrtf(fmaf(-mI2, mI2, qI2 * rD) + 1e-5f);
    float nR1 = -mR1 * vR1, nI1 = -mI1 * vI1, nR2 = -mR2 * vR2, nI2 = -mI2 * vI2;

    float s2A = 0.f, s2B = 0.f, q2A = 0.f, q2B = 0.f, dA = 0.f, dB = 0.f;
#pragma unroll
    for (int v = 0; v < 8; ++v) {
        float2 f1 = __half22float2(R1h[v]);
        float2 g1 = __half22float2(I1h[v]);
        float2 f2 = __half22float2(R2h[v]);
        float2 g2 = __half22float2(I2h[v]);
        float2 fa = __half22float2((v < 4) ? h2(rwal, v) : h2(rwah, v - 4));
        float2 fb = __half22float2((v < 4) ? h2(rwbl, v) : h2(rwbh, v - 4));
#pragma unroll
        for (int c = 0; c < 2; ++c) {
            float x1v = c ? f1.y : f1.x;
            float y1v = c ? g1.y : g1.x;
            float x2v = c ? f2.y : f2.x;
            float y2v = c ? g2.y : g2.x;
            float wav = c ? fa.y : fa.x;
            float wbv = c ? fb.y : fb.x;
            float r1  = fmaf(x1v, vR1, nR1);
            float i1v = fmaf(y1v, vI1, nI1);
            float r2  = fmaf(x2v, vR2, nR2);
            float i2v = fmaf(y2v, vI2, nI2);
            float rc = fmaf(r1, r2, -i1v * i2v);
            float ic = fmaf(r1, i2v, i1v * r2);
            s2A += rc;
            s2B += ic;
            q2A = fmaf(rc, rc, q2A);
            q2B = fmaf(ic, ic, q2B);
            dA = fmaf(rc, wav, dA);
            dB = fmaf(ic, wbv, dB);
        }
    }

    // Tree B: 6 values, 4-stage segment butterfly
#pragma unroll
    for (int o = 8; o; o >>= 1) {
        s2A += __shfl_xor_sync(0xffffffffu, s2A, o);
        s2B += __shfl_xor_sync(0xffffffffu, s2B, o);
        q2A += __shfl_xor_sync(0xffffffffu, q2A, o);
        q2B += __shfl_xor_sync(0xffffffffu, q2B, o);
        dA  += __shfl_xor_sync(0xffffffffu, dA, o);
        dB  += __shfl_xor_sync(0xffffffffu, dB, o);
    }

    if (sl == 0 && live) {
        float sAr = RS[rr * 2], sBr = RS[rr * 2 + 1];
        float mA = s2A * rD;
        float mB = s2B * rD;
        float invA = rsqrtf(fmaf(-mA, mA, q2A * rD) + 1e-5f);
        float invB = rsqrtf(fmaf(-mB, mB, q2B * rD) + 1e-5f);
        float acc = invA * fmaf(-mA, sAr, dA) + invB * fmaf(-mB, sBr, dB);
        out[e] = 1.f / (1.f + expf(-acc));
    }
}

// ---------------------------------------------------------------------------
extern "C" void kernel_launch(void* const* d_in, const int* in_sizes, int n_in,
                              void* d_out, int out_size) {
    const float* drug_fp   = (const float*)d_in[0];
    const float* drug_init = (const float*)d_in[1];
    const float* x1        = (const float*)d_in[2];
    const float* x2        = (const float*)d_in[3];
    const float* W_fp      = (const float*)d_in[4];
    const float* W_skip    = (const float*)d_in[5];
    const float* wr        = (const float*)d_in[6];
    const float* wi        = (const float*)d_in[7];
    const int*   idx1      = (const int*)d_in[8];
    const int*   idx2      = (const int*)d_in[9];
    const int*   idx3      = (const int*)d_in[10];
    float*       out       = (float*)d_out;
    int E = in_sizes[8];

    float *fpn, *NS, *RS;
    __half *P, *wAB;
    cudaGetSymbolAddress((void**)&fpn, g_fpn);
    cudaGetSymbolAddress((void**)&P,   g_P);
    cudaGetSymbolAddress((void**)&wAB, g_wAB);
    cudaGetSymbolAddress((void**)&NS,  g_NS);
    cudaGetSymbolAddress((void**)&RS,  g_RS);

    // 1) fp_n = elu(LN(drug_fp))
    lnelu512_kernel<<<(NN * 32 + 255) / 256, 256>>>(drug_fp, fpn);

    // 2) pack x1/x2 and relation weights (fp16)
    pack_kernel<<<(NN * DD + 255) / 256, 256>>>(x1, x2, wr, wi, P, wAB);

    // 3) GEMMs -> slots 2/3 of P (fp16)
    dim3 gg((NN + 63) / 64, DD / 64, 2);
    gemm_nt_kernel<<<gg, 256>>>(fpn, W_fp, drug_init, W_skip, P);

    // 4) per-node and per-relation sums
    nodestat_kernel<<<(NN * 32 + 255) / 256, 256>>>(P, NS);
    relstat_kernel<<<(RR * 32 + 255) / 256, 256>>>(wAB, RS);

    // 5) edge phase: two edges per warp (16 edges per 256-thread block)
    edge_kernel<<<(E + 15) / 16, 256>>>(P, wAB, NS, RS, idx1, idx2, idx3, out, E);
}